// round 1
// baseline (speedup 1.0000x reference)
#include <cuda_runtime.h>

// Problem constants
#define BB 512      // batch
#define TT 1024     // seq len
#define II 50       // input size
#define HH 32       // hidden
#define GG 128      // 4*H gates
#define BT (BB*TT)

typedef unsigned long long u64;

// ---------------- scratch (device globals: no allocation allowed) ----------------
__device__ float   g_xp[2][TT][BB][GG];        // 512MB: input projections (dir-reversed for dir=1)
__device__ float   g_yp[2][BT];                // per-direction partial outputs
__device__ float4  g_wih4[2][II][GG/4];        // w_ih pair-major: [dir][k][j4] = gates 4j4..4j4+3 at col k
__device__ float2  g_whh2[2][HH][GG/2];        // w_hh pair-major: [dir][k][r2] = gates {2r2,2r2+1} at col k
__device__ float2  g_bias2[2][GG/2];           // b_ih+b_hh as gate pairs
__device__ float   g_weff[2*HH];               // collapsed FC head weight (64)
__device__ float   g_beff;                     // collapsed FC head bias

// ---------------- f32x2 helpers ----------------
__device__ __forceinline__ u64 pk2(float lo, float hi) {
    u64 r; asm("mov.b64 %0, {%1,%2};" : "=l"(r) : "f"(lo), "f"(hi)); return r;
}
__device__ __forceinline__ float2 upk2(u64 v) {
    float2 r; asm("mov.b64 {%0,%1}, %2;" : "=f"(r.x), "=f"(r.y) : "l"(v)); return r;
}
__device__ __forceinline__ void fma2(u64& d, u64 a, u64 b) {
    asm("fma.rn.f32x2 %0, %1, %2, %0;" : "+l"(d) : "l"(a), "l"(b));
}

// ---------------- fast transcendentals (MUFU, rel err ~2^-22) ----------------
__device__ __forceinline__ float fex2(float x) { float r; asm("ex2.approx.f32 %0, %1;" : "=f"(r) : "f"(x)); return r; }
__device__ __forceinline__ float frcp(float x) { float r; asm("rcp.approx.f32 %0, %1;" : "=f"(r) : "f"(x)); return r; }
__device__ __forceinline__ float sigm(float x) {
    // 1/(1+2^(-x*log2e)); saturates correctly at +/-inf
    return frcp(1.0f + fex2(-1.4426950408889634f * x));
}
__device__ __forceinline__ float tanhx(float x) {
    // tanh = 1 - 2/(1+2^(2x*log2e))
    return 1.0f - 2.0f * frcp(1.0f + fex2(2.8853900817779268f * x));
}

// ---------------- prep: weight re-layouts + FC-head collapse ----------------
__global__ void prep_kernel(const float* __restrict__ wih_f, const float* __restrict__ whh_f,
                            const float* __restrict__ bih_f, const float* __restrict__ bhh_f,
                            const float* __restrict__ wih_r, const float* __restrict__ whh_r,
                            const float* __restrict__ bih_r, const float* __restrict__ bhh_r,
                            const float* __restrict__ fc1w, const float* __restrict__ fc1b,
                            const float* __restrict__ fc3w, const float* __restrict__ fc3b) {
    int gt = blockIdx.x * blockDim.x + threadIdx.x;
    int nth = gridDim.x * blockDim.x;

    // collapsed FC head: w_eff[j] = sum_k fc3w[k]*fc1w[k,j]  (fc1w is (64,64) row-major)
    for (int j = gt; j < 2 * HH; j += nth) {
        float s = 0.f;
        #pragma unroll 8
        for (int k = 0; k < 2 * HH; k++) s = fmaf(fc3w[k], fc1w[k * (2 * HH) + j], s);
        g_weff[j] = s;
    }
    if (gt == 0) {
        float s = fc3b[0];
        for (int k = 0; k < 2 * HH; k++) s = fmaf(fc3w[k], fc1b[k], s);
        g_beff = s;
    }
    // w_hh pairs: [dir][k][r2] = { w[2r2,k], w[2r2+1,k] }   (w_hh is (128,32) row-major)
    for (int n = gt; n < 2 * HH * 64; n += nth) {
        int dir = n >> 11; int rem = n & 2047; int k = rem >> 6; int r2 = rem & 63;
        const float* src = dir ? whh_r : whh_f;
        ((float2*)g_whh2)[n] = make_float2(src[(2 * r2) * HH + k], src[(2 * r2 + 1) * HH + k]);
    }
    // w_ih quads: [dir][k][j4] = { w[4j4,k], w[4j4+1,k], w[4j4+2,k], w[4j4+3,k] }  (w_ih is (128,50))
    for (int n = gt; n < 2 * II * 32; n += nth) {
        int dir = n / (II * 32); int rem = n - dir * (II * 32); int k = rem >> 5; int j4 = rem & 31;
        const float* src = dir ? wih_r : wih_f;
        ((float4*)g_wih4)[n] = make_float4(src[(4 * j4) * II + k], src[(4 * j4 + 1) * II + k],
                                           src[(4 * j4 + 2) * II + k], src[(4 * j4 + 3) * II + k]);
    }
    // bias pairs (b_ih + b_hh)
    for (int n = gt; n < 2 * 64; n += nth) {
        int dir = n >> 6; int r2 = n & 63;
        const float* bi = dir ? bih_r : bih_f;
        const float* bh = dir ? bhh_r : bhh_f;
        ((float2*)g_bias2)[n] = make_float2(bi[2 * r2] + bh[2 * r2], bi[2 * r2 + 1] + bh[2 * r2 + 1]);
    }
}

// ---------------- input projection: xp[dir][t][b][128] = x[b,t,:] @ w_ih^T + bias ----------------
// Tile: 64 rows (b*T+t flattened, contiguous in x) x 128 gates per CTA.
// Thread (rp = tid&31, qp = tid>>5): rows {rp, rp+32}, gates 8qp..8qp+7 (4 f32x2 pairs).
__global__ void __launch_bounds__(512, 2) proj_kernel(const float* __restrict__ x) {
    __shared__ float4 wq[II][32];        // [k][j4], identical layout to g_wih4[dir]
    __shared__ float  xs[II][65];        // transposed x tile, padded pitch (bank-friendly)

    const int dir = blockIdx.y;
    const int m0  = blockIdx.x * 64;
    const int tid = threadIdx.x;

    // stage weights (coalesced copy)
    {
        const float4* wsrc = &g_wih4[dir][0][0];
        for (int n = tid; n < II * 32; n += 512) ((float4*)wq)[n] = wsrc[n];
    }
    // stage x transposed: n = r*II + i  ->  xs[i][r]
    for (int n = tid; n < 64 * II; n += 512) {
        float v = x[m0 * II + n];
        int r = n / II, i = n - r * II;
        xs[i][r] = v;
    }
    __syncthreads();

    const int rp = tid & 31;
    const int qp = tid >> 5;

    u64 acc[8];
    {
        ulonglong2 bA = *(const ulonglong2*)&g_bias2[dir][4 * qp];
        ulonglong2 bB = *(const ulonglong2*)&g_bias2[dir][4 * qp + 2];
        acc[0] = bA.x; acc[1] = bA.y; acc[2] = bB.x; acc[3] = bB.y;
        acc[4] = bA.x; acc[5] = bA.y; acc[6] = bB.x; acc[7] = bB.y;
    }

    #pragma unroll 10
    for (int k = 0; k < II; k++) {
        float xa = xs[k][rp];
        float xb = xs[k][rp + 32];
        u64 xa2 = pk2(xa, xa);
        u64 xb2 = pk2(xb, xb);
        ulonglong2 wA = *(const ulonglong2*)&wq[k][2 * qp];       // pairs p0,p1 (broadcast)
        ulonglong2 wB = *(const ulonglong2*)&wq[k][2 * qp + 1];   // pairs p2,p3
        fma2(acc[0], wA.x, xa2); fma2(acc[1], wA.y, xa2);
        fma2(acc[2], wB.x, xa2); fma2(acc[3], wB.y, xa2);
        fma2(acc[4], wA.x, xb2); fma2(acc[5], wA.y, xb2);
        fma2(acc[6], wB.x, xb2); fma2(acc[7], wB.y, xb2);
    }

    // write both rows: 32 bytes of consecutive gates per row (full sectors)
    #pragma unroll
    for (int rr = 0; rr < 2; rr++) {
        int m = m0 + rp + rr * 32;
        int b = m >> 10;                 // m / T
        int t = m & (TT - 1);
        int tt = dir ? (TT - 1 - t) : t;
        float* dst = &g_xp[dir][tt][b][8 * qp];
        ulonglong2 s0, s1;
        s0.x = acc[rr * 4 + 0]; s0.y = acc[rr * 4 + 1];
        s1.x = acc[rr * 4 + 2]; s1.y = acc[rr * 4 + 3];
        *(ulonglong2*)dst       = s0;
        *(ulonglong2*)(dst + 4) = s1;
    }
}

// ---------------- recurrent scan: one CTA = 4 batch elements, one direction ----------------
// Compute role: thread (bl = tid>>6, r2 = tid&63): gate-pair {2r2,2r2+1} of batch bl.
//   W_hh register-resident as 32 f32x2 pairs; h broadcast from SMEM (dup float2, LDS.128 quads).
// Epilogue role (tid<128): thread (eb = tid>>5, ej = tid&31): cell j=ej of batch eb; c is thread-resident.
__global__ void __launch_bounds__(256, 2) lstm_kernel() {
    const int dir = blockIdx.y;
    const int b0  = blockIdx.x * 4;
    const int tid = threadIdx.x;

    __shared__ float4 h4s[4][HH / 2];                 // duplicated h pairs: h4s[b][k2] = {h2k,h2k,h2k+1,h2k+1}
    __shared__ __align__(16) float zbuf[4][GG];

    const int bl = tid >> 6;
    const int r2 = tid & 63;

    // register-resident W_hh pairs for this gate-pair
    u64 w2[HH];
    #pragma unroll
    for (int k = 0; k < HH; k++)
        w2[k] = *(const u64*)&g_whh2[dir][k][r2];

    const int eb = tid >> 5, ej = tid & 31;
    float c = 0.f;
    float wej = (tid < 128) ? g_weff[dir * HH + ej] : 0.f;

    if (tid < 128) {
        float* hp = (float*)h4s + eb * (2 * HH) + 2 * ej;
        *(float2*)hp = make_float2(0.f, 0.f);
    }

    const float* xp_base = &g_xp[dir][0][0][0];
    const int xoff = (b0 + bl) * GG + 2 * r2;
    u64 xnext = *(const u64*)(xp_base + xoff);        // prefetch t=0
    __syncthreads();

    for (int t = 0; t < TT; t++) {
        // z = xp + W_hh @ h   (32 packed FMAs, all h loads are warp-broadcast)
        u64 acc = xnext;
        #pragma unroll
        for (int k2 = 0; k2 < HH / 2; k2++) {
            ulonglong2 hq = *(const ulonglong2*)&h4s[bl][k2];
            fma2(acc, w2[2 * k2],     hq.x);
            fma2(acc, w2[2 * k2 + 1], hq.y);
        }
        *(u64*)&zbuf[bl][2 * r2] = acc;
        __syncthreads();

        // prefetch next step's xp under the epilogue
        int tn = (t + 1 < TT) ? (t + 1) : t;
        xnext = *(const u64*)(xp_base + tn * (BB * GG) + xoff);

        if (tid < 128) {
            float zi = zbuf[eb][ej];
            float zf = zbuf[eb][HH + ej];
            float zg = zbuf[eb][2 * HH + ej];
            float zo = zbuf[eb][3 * HH + ej];
            float fg = sigm(zf), ig = sigm(zi), gg = tanhx(zg), og = sigm(zo);
            c = fmaf(fg, c, ig * gg);
            float h = og * tanhx(c);
            float* hp = (float*)h4s + eb * (2 * HH) + 2 * ej;
            *(float2*)hp = make_float2(h, h);
            // fused FC head: warp-reduce h . w_eff  (one warp == one batch element)
            float r = h * wej;
            r += __shfl_xor_sync(0xffffffffu, r, 16);
            r += __shfl_xor_sync(0xffffffffu, r, 8);
            r += __shfl_xor_sync(0xffffffffu, r, 4);
            r += __shfl_xor_sync(0xffffffffu, r, 2);
            r += __shfl_xor_sync(0xffffffffu, r, 1);
            if (ej == 0) {
                int tout = dir ? (TT - 1 - t) : t;
                g_yp[dir][(b0 + eb) * TT + tout] = r;
            }
        }
        __syncthreads();
    }
}

// ---------------- combine: out = yf + yr + b_eff ----------------
__global__ void combine_kernel(float* __restrict__ out) {
    int i = blockIdx.x * blockDim.x + threadIdx.x;
    if (i < BT) out[i] = g_yp[0][i] + g_yp[1][i] + g_beff;
}

extern "C" void kernel_launch(void* const* d_in, const int* in_sizes, int n_in,
                              void* d_out, int out_size) {
    const float* x     = (const float*)d_in[0];
    const float* wih_f = (const float*)d_in[1];
    const float* whh_f = (const float*)d_in[2];
    const float* bih_f = (const float*)d_in[3];
    const float* bhh_f = (const float*)d_in[4];
    const float* wih_r = (const float*)d_in[5];
    const float* whh_r = (const float*)d_in[6];
    const float* bih_r = (const float*)d_in[7];
    const float* bhh_r = (const float*)d_in[8];
    const float* fc1w  = (const float*)d_in[9];
    const float* fc1b  = (const float*)d_in[10];
    const float* fc3w  = (const float*)d_in[11];
    const float* fc3b  = (const float*)d_in[12];
    float* out = (float*)d_out;

    prep_kernel<<<32, 256>>>(wih_f, whh_f, bih_f, bhh_f,
                             wih_r, whh_r, bih_r, bhh_r,
                             fc1w, fc1b, fc3w, fc3b);

    dim3 pg(BT / 64, 2);
    proj_kernel<<<pg, 512>>>(x);

    dim3 lg(BB / 4, 2);
    lstm_kernel<<<lg, 256>>>();

    combine_kernel<<<(BT + 255) / 256, 256>>>(out);
}

// round 2
// speedup vs baseline: 1.0303x; 1.0303x over previous
#include <cuda_runtime.h>

// Problem constants
#define BB 512      // batch
#define TT 1024     // seq len
#define II 50       // input size
#define HH 32       // hidden
#define GG 128      // 4*H gates
#define BT (BB*TT)

typedef unsigned long long u64;

// ---------------- scratch (device globals: no allocation allowed) ----------------
// xp quads: [dir][t][b][cell] = {zi, zf, zg, zo}  (dir=1 stored time-reversed)
__device__ float4 g_xp4[2][TT][BB][HH];            // 512 MB
__device__ float  g_yp[2][BT];                     // per-direction partial outputs
// proj weights: [dir][k][q] = {w_i[q,k], w_f[q,k], w_i[q+16,k], w_f[q+16,k]}
__device__ float4 g_wif4p[2][II][16];
__device__ float4 g_wgo4p[2][II][16];
__device__ float4 g_bias4[2][HH];                  // {bi,bf,bg,bo} per cell (b_ih+b_hh)
// recurrent weights: [dir][k][j] = {whh[j,k], whh[H+j,k]} / {whh[2H+j,k], whh[3H+j,k]}
__device__ float2 g_whif2[2][HH][HH];
__device__ float2 g_whgo2[2][HH][HH];
__device__ float  g_weff[2*HH];                    // collapsed FC head weight (64)
__device__ float  g_beff;                          // collapsed FC head bias

// ---------------- f32x2 helpers ----------------
__device__ __forceinline__ u64 pk2(float lo, float hi) {
    u64 r; asm("mov.b64 %0, {%1,%2};" : "=l"(r) : "f"(lo), "f"(hi)); return r;
}
__device__ __forceinline__ float2 upk2(u64 v) {
    float2 r; asm("mov.b64 {%0,%1}, %2;" : "=f"(r.x), "=f"(r.y) : "l"(v)); return r;
}
__device__ __forceinline__ void fma2(u64& d, u64 a, u64 b) {
    asm("fma.rn.f32x2 %0, %1, %2, %0;" : "+l"(d) : "l"(a), "l"(b));
}
__device__ __forceinline__ u64 add2(u64 a, u64 b) {
    u64 r; asm("add.rn.f32x2 %0, %1, %2;" : "=l"(r) : "l"(a), "l"(b)); return r;
}

// ---------------- fast transcendentals (MUFU, rel err ~2^-22) ----------------
__device__ __forceinline__ float fex2(float x) { float r; asm("ex2.approx.f32 %0, %1;" : "=f"(r) : "f"(x)); return r; }
__device__ __forceinline__ float frcp(float x) { float r; asm("rcp.approx.f32 %0, %1;" : "=f"(r) : "f"(x)); return r; }
__device__ __forceinline__ float sigm(float x) {
    return frcp(1.0f + fex2(-1.4426950408889634f * x));
}
__device__ __forceinline__ float tanhx(float x) {
    return 1.0f - 2.0f * frcp(1.0f + fex2(2.8853900817779268f * x));
}

// ---------------- prep: weight re-layouts + FC-head collapse ----------------
__global__ void prep_kernel(const float* __restrict__ wih_f, const float* __restrict__ whh_f,
                            const float* __restrict__ bih_f, const float* __restrict__ bhh_f,
                            const float* __restrict__ wih_r, const float* __restrict__ whh_r,
                            const float* __restrict__ bih_r, const float* __restrict__ bhh_r,
                            const float* __restrict__ fc1w, const float* __restrict__ fc1b,
                            const float* __restrict__ fc3w, const float* __restrict__ fc3b) {
    int gt = blockIdx.x * blockDim.x + threadIdx.x;
    int nth = gridDim.x * blockDim.x;

    // collapsed FC head: w_eff[j] = sum_k fc3w[k]*fc1w[k,j]  (fc1w is (64,64) row-major)
    for (int j = gt; j < 2 * HH; j += nth) {
        float s = 0.f;
        #pragma unroll 8
        for (int k = 0; k < 2 * HH; k++) s = fmaf(fc3w[k], fc1w[k * (2 * HH) + j], s);
        g_weff[j] = s;
    }
    if (gt == 0) {
        float s = fc3b[0];
        for (int k = 0; k < 2 * HH; k++) s = fmaf(fc3w[k], fc1b[k], s);
        g_beff = s;
    }
    // proj weight quads (w_ih is (128, 50) row-major; gate rows: i=0..31, f=32..63, g=64..95, o=96..127)
    for (int n = gt; n < 2 * II * 16; n += nth) {
        int dir = n / (II * 16); int rem = n - dir * (II * 16); int k = rem >> 4; int q = rem & 15;
        const float* src = dir ? wih_r : wih_f;
        g_wif4p[dir][k][q] = make_float4(src[q * II + k],        src[(32 + q) * II + k],
                                         src[(q + 16) * II + k], src[(48 + q) * II + k]);
        g_wgo4p[dir][k][q] = make_float4(src[(64 + q) * II + k], src[(96 + q) * II + k],
                                         src[(80 + q) * II + k], src[(112 + q) * II + k]);
    }
    // bias quads
    for (int n = gt; n < 2 * HH; n += nth) {
        int dir = n >> 5; int j = n & 31;
        const float* bi = dir ? bih_r : bih_f;
        const float* bh = dir ? bhh_r : bhh_f;
        g_bias4[dir][j] = make_float4(bi[j] + bh[j],           bi[32 + j] + bh[32 + j],
                                      bi[64 + j] + bh[64 + j], bi[96 + j] + bh[96 + j]);
    }
    // recurrent weight pairs (w_hh is (128, 32) row-major)
    for (int n = gt; n < 2 * HH * HH; n += nth) {
        int dir = n >> 10; int k = (n >> 5) & 31; int j = n & 31;
        const float* src = dir ? whh_r : whh_f;
        g_whif2[dir][k][j] = make_float2(src[j * HH + k],        src[(32 + j) * HH + k]);
        g_whgo2[dir][k][j] = make_float2(src[(64 + j) * HH + k], src[(96 + j) * HH + k]);
    }
}

// ---------------- input projection -> per-cell gate quads ----------------
// Tile: 64 rows (flattened b*T+t) x 128 gates per CTA, 512 threads.
// Thread (rp = tid>>4 in 0..31, qp = tid&15): rows {rp, rp+32}, cells {qp, qp+16}.
__global__ void __launch_bounds__(512, 2) proj_kernel(const float* __restrict__ x) {
    __shared__ float4 wifs[II][16];
    __shared__ float4 wgos[II][16];
    __shared__ float  xs[II][64];        // transposed x tile

    const int dir = blockIdx.y;
    const int m0  = blockIdx.x * 64;
    const int tid = threadIdx.x;

    // stage weights
    for (int n = tid; n < II * 16; n += 512) {
        ((float4*)wifs)[n] = (&g_wif4p[dir][0][0])[n];
        ((float4*)wgos)[n] = (&g_wgo4p[dir][0][0])[n];
    }
    // stage x transposed: n = r*II + i -> xs[i][r]
    for (int n = tid; n < 64 * II; n += 512) {
        float v = x[m0 * II + n];
        int r = n / II, i = n - r * II;
        xs[i][r] = v;
    }
    __syncthreads();

    const int qp = tid & 15;
    const int rp = tid >> 4;

    u64 if_a0, if_a1, go_a0, go_a1, if_b0, if_b1, go_b0, go_b1;
    {
        ulonglong2 b0 = *(const ulonglong2*)&g_bias4[dir][qp];
        ulonglong2 b1 = *(const ulonglong2*)&g_bias4[dir][qp + 16];
        if_a0 = b0.x; go_a0 = b0.y; if_a1 = b1.x; go_a1 = b1.y;
        if_b0 = b0.x; go_b0 = b0.y; if_b1 = b1.x; go_b1 = b1.y;
    }

    #pragma unroll 10
    for (int k = 0; k < II; k++) {
        float xa = xs[k][rp];
        float xb = xs[k][rp + 32];
        u64 xa2 = pk2(xa, xa);
        u64 xb2 = pk2(xb, xb);
        ulonglong2 wif = *(const ulonglong2*)&wifs[k][qp];   // .x = if-pair cell qp, .y = cell qp+16
        ulonglong2 wgo = *(const ulonglong2*)&wgos[k][qp];
        fma2(if_a0, wif.x, xa2); fma2(if_a1, wif.y, xa2);
        fma2(go_a0, wgo.x, xa2); fma2(go_a1, wgo.y, xa2);
        fma2(if_b0, wif.x, xb2); fma2(if_b1, wif.y, xb2);
        fma2(go_b0, wgo.x, xb2); fma2(go_b1, wgo.y, xb2);
    }

    // write gate quads {zi,zf,zg,zo}: fully coalesced (16 lanes x 16B contiguous per row)
    #pragma unroll
    for (int rr = 0; rr < 2; rr++) {
        int m = m0 + rp + rr * 32;
        int b = m >> 10;
        int t = m & (TT - 1);
        int tt = dir ? (TT - 1 - t) : t;
        float4* dst = &g_xp4[dir][tt][b][0];
        ulonglong2 s0, s1;
        if (rr == 0) { s0.x = if_a0; s0.y = go_a0; s1.x = if_a1; s1.y = go_a1; }
        else         { s0.x = if_b0; s0.y = go_b0; s1.x = if_b1; s1.y = go_b1; }
        *(ulonglong2*)&dst[qp]      = s0;
        *(ulonglong2*)&dst[qp + 16] = s1;
    }
}

// ---------------- recurrent scan: one WARP = one (dir, batch); barrier-free ----------------
// Lane j owns cell j: gates (i,f,g,o) packed as two f32x2 accumulators.
// W_hh register-resident (64 f32x2 pairs). h broadcast via per-warp SMEM dup pairs,
// double-buffered -> single __syncwarp per step. xp LDG.128 ring-prefetched 4 deep.
__global__ void __launch_bounds__(128, 2) lstm_kernel() {
    const int tid  = threadIdx.x;
    const int wrp  = tid >> 5;
    const int j    = tid & 31;
    const int gw   = blockIdx.x * 4 + wrp;       // 0..1023
    const int dir  = gw >> 9;
    const int b    = gw & 511;

    __shared__ __align__(16) float2 hbuf[4][2][HH];   // [warp][buf][k] = {h_k, h_k}

    // register-resident W_hh pairs for this cell
    u64 wif[HH], wgo[HH];
    #pragma unroll
    for (int k = 0; k < HH; k++) {
        wif[k] = *(const u64*)&g_whif2[dir][k][j];
        wgo[k] = *(const u64*)&g_whgo2[dir][k][j];
    }

    const float wej = g_weff[dir * HH + j];

    hbuf[wrp][0][j] = make_float2(0.f, 0.f);
    __syncwarp();

    const float4* __restrict__ xp = &g_xp4[dir][0][b][j];
    const int XS = BB * HH;                       // float4 stride per time step

    // prefetch ring, depth 4
    float4 xr[4];
    #pragma unroll
    for (int p = 0; p < 4; p++) xr[p] = xp[p * XS];

    float c = 0.f;
    int pb = 0;

    #pragma unroll 4
    for (int t = 0; t < TT; t++) {
        float4 xc = xr[t & 3];
        u64 aif0 = pk2(xc.x, xc.y);               // {zi, zf}
        u64 ago0 = pk2(xc.z, xc.w);               // {zg, zo}
        u64 aif1 = pk2(0.f, 0.f);
        u64 ago1 = pk2(0.f, 0.f);

        const float2* hb = hbuf[wrp][pb];
        #pragma unroll
        for (int k2 = 0; k2 < HH / 2; k2++) {
            ulonglong2 hq = *(const ulonglong2*)&hb[2 * k2];   // uniform broadcast LDS.128
            fma2(aif0, wif[2 * k2],     hq.x);
            fma2(aif1, wif[2 * k2 + 1], hq.y);
            fma2(ago0, wgo[2 * k2],     hq.x);
            fma2(ago1, wgo[2 * k2 + 1], hq.y);
        }

        // prefetch t+4 (slot reuse)
        int tn = (t + 4 < TT) ? (t + 4) : (TT - 1);
        xr[t & 3] = xp[tn * XS];

        float2 zif = upk2(add2(aif0, aif1));
        float2 zgo = upk2(add2(ago0, ago1));
        float ig = sigm(zif.x), fg = sigm(zif.y);
        float gg = tanhx(zgo.x), og = sigm(zgo.y);
        c = fmaf(fg, c, ig * gg);
        float h = og * tanhx(c);

        hbuf[wrp][pb ^ 1][j] = make_float2(h, h);

        // fused FC head (off critical path: no barrier follows)
        float r = h * wej;
        r += __shfl_xor_sync(0xffffffffu, r, 16);
        r += __shfl_xor_sync(0xffffffffu, r, 8);
        r += __shfl_xor_sync(0xffffffffu, r, 4);
        r += __shfl_xor_sync(0xffffffffu, r, 2);
        r += __shfl_xor_sync(0xffffffffu, r, 1);
        if (j == 0) {
            int tout = dir ? (TT - 1 - t) : t;
            g_yp[dir][b * TT + tout] = r;
        }

        __syncwarp();
        pb ^= 1;
    }
}

// ---------------- combine: out = yf + yr + b_eff ----------------
__global__ void combine_kernel(float* __restrict__ out) {
    int i = blockIdx.x * blockDim.x + threadIdx.x;
    if (i < BT) out[i] = g_yp[0][i] + g_yp[1][i] + g_beff;
}

extern "C" void kernel_launch(void* const* d_in, const int* in_sizes, int n_in,
                              void* d_out, int out_size) {
    const float* x     = (const float*)d_in[0];
    const float* wih_f = (const float*)d_in[1];
    const float* whh_f = (const float*)d_in[2];
    const float* bih_f = (const float*)d_in[3];
    const float* bhh_f = (const float*)d_in[4];
    const float* wih_r = (const float*)d_in[5];
    const float* whh_r = (const float*)d_in[6];
    const float* bih_r = (const float*)d_in[7];
    const float* bhh_r = (const float*)d_in[8];
    const float* fc1w  = (const float*)d_in[9];
    const float* fc1b  = (const float*)d_in[10];
    const float* fc3w  = (const float*)d_in[11];
    const float* fc3b  = (const float*)d_in[12];
    float* out = (float*)d_out;

    prep_kernel<<<32, 256>>>(wih_f, whh_f, bih_f, bhh_f,
                             wih_r, whh_r, bih_r, bhh_r,
                             fc1w, fc1b, fc3w, fc3b);

    dim3 pg(BT / 64, 2);
    proj_kernel<<<pg, 512>>>(x);

    lstm_kernel<<<256, 128>>>();

    combine_kernel<<<(BT + 255) / 256, 256>>>(out);
}

// round 5
// speedup vs baseline: 1.1336x; 1.1003x over previous
#include <cuda_runtime.h>

// Problem constants
#define BB 512      // batch
#define TT 1024     // seq len
#define II 50       // input size
#define HH 32       // hidden
#define GG 128      // 4*H gates
#define BT (BB*TT)

typedef unsigned long long u64;

// ---------------- scratch (device globals: no allocation allowed) ----------------
// xp quads: [dir][t][b][cell] = {zi, zf, zg, zo}  (dir=1 stored time-reversed)
__device__ float4 g_xp4[2][TT][BB][HH];            // 512 MB
__device__ float  g_yp[2][BT];                     // per-direction partial outputs
// proj weights: [dir][k][q] = {w_i[q,k], w_f[q,k], w_i[q+16,k], w_f[q+16,k]}
__device__ float4 g_wif4p[2][II][16];
__device__ float4 g_wgo4p[2][II][16];
__device__ float4 g_bias4[2][HH];                  // {bi,bf,bg,bo} per cell (b_ih+b_hh)
// recurrent weights: [dir][k][j] = {whh[j,k], whh[H+j,k]} / {whh[2H+j,k], whh[3H+j,k]}
__device__ float2 g_whif2[2][HH][HH];
__device__ float2 g_whgo2[2][HH][HH];
__device__ float  g_weff[2*HH];                    // collapsed FC head weight (64)
__device__ float  g_beff;                          // collapsed FC head bias

// ---------------- f32x2 helpers ----------------
__device__ __forceinline__ u64 pk2(float lo, float hi) {
    u64 r; asm("mov.b64 %0, {%1,%2};" : "=l"(r) : "f"(lo), "f"(hi)); return r;
}
__device__ __forceinline__ float2 upk2(u64 v) {
    float2 r; asm("mov.b64 {%0,%1}, %2;" : "=f"(r.x), "=f"(r.y) : "l"(v)); return r;
}
__device__ __forceinline__ void fma2(u64& d, u64 a, u64 b) {
    asm("fma.rn.f32x2 %0, %1, %2, %0;" : "+l"(d) : "l"(a), "l"(b));
}
__device__ __forceinline__ u64 add2(u64 a, u64 b) {
    u64 r; asm("add.rn.f32x2 %0, %1, %2;" : "=l"(r) : "l"(a), "l"(b)); return r;
}

// ---------------- fast transcendentals (MUFU, rel err ~2^-22) ----------------
__device__ __forceinline__ float fex2(float x) { float r; asm("ex2.approx.f32 %0, %1;" : "=f"(r) : "f"(x)); return r; }
__device__ __forceinline__ float frcp(float x) { float r; asm("rcp.approx.f32 %0, %1;" : "=f"(r) : "f"(x)); return r; }
__device__ __forceinline__ float sigm(float x) {
    return frcp(1.0f + fex2(-1.4426950408889634f * x));
}
__device__ __forceinline__ float tanhx(float x) {
    return 1.0f - 2.0f * frcp(1.0f + fex2(2.8853900817779268f * x));
}

// ---------------- prep: weight re-layouts + FC-head collapse ----------------
__global__ void prep_kernel(const float* __restrict__ wih_f, const float* __restrict__ whh_f,
                            const float* __restrict__ bih_f, const float* __restrict__ bhh_f,
                            const float* __restrict__ wih_r, const float* __restrict__ whh_r,
                            const float* __restrict__ bih_r, const float* __restrict__ bhh_r,
                            const float* __restrict__ fc1w, const float* __restrict__ fc1b,
                            const float* __restrict__ fc3w, const float* __restrict__ fc3b) {
    int gt = blockIdx.x * blockDim.x + threadIdx.x;
    int nth = gridDim.x * blockDim.x;

    // collapsed FC head: w_eff[j] = sum_k fc3w[k]*fc1w[k,j]
    for (int j = gt; j < 2 * HH; j += nth) {
        float s = 0.f;
        #pragma unroll 8
        for (int k = 0; k < 2 * HH; k++) s = fmaf(fc3w[k], fc1w[k * (2 * HH) + j], s);
        g_weff[j] = s;
    }
    if (gt == 0) {
        float s = fc3b[0];
        for (int k = 0; k < 2 * HH; k++) s = fmaf(fc3w[k], fc1b[k], s);
        g_beff = s;
    }
    // proj weight quads (w_ih is (128, 50) row-major; gate rows: i=0..31, f=32..63, g=64..95, o=96..127)
    for (int n = gt; n < 2 * II * 16; n += nth) {
        int dir = n / (II * 16); int rem = n - dir * (II * 16); int k = rem >> 4; int q = rem & 15;
        const float* src = dir ? wih_r : wih_f;
        g_wif4p[dir][k][q] = make_float4(src[q * II + k],        src[(32 + q) * II + k],
                                         src[(q + 16) * II + k], src[(48 + q) * II + k]);
        g_wgo4p[dir][k][q] = make_float4(src[(64 + q) * II + k], src[(96 + q) * II + k],
                                         src[(80 + q) * II + k], src[(112 + q) * II + k]);
    }
    // bias quads
    for (int n = gt; n < 2 * HH; n += nth) {
        int dir = n >> 5; int j = n & 31;
        const float* bi = dir ? bih_r : bih_f;
        const float* bh = dir ? bhh_r : bhh_f;
        g_bias4[dir][j] = make_float4(bi[j] + bh[j],           bi[32 + j] + bh[32 + j],
                                      bi[64 + j] + bh[64 + j], bi[96 + j] + bh[96 + j]);
    }
    // recurrent weight pairs (w_hh is (128, 32) row-major)
    for (int n = gt; n < 2 * HH * HH; n += nth) {
        int dir = n >> 10; int k = (n >> 5) & 31; int j = n & 31;
        const float* src = dir ? whh_r : whh_f;
        g_whif2[dir][k][j] = make_float2(src[j * HH + k],        src[(32 + j) * HH + k]);
        g_whgo2[dir][k][j] = make_float2(src[(64 + j) * HH + k], src[(96 + j) * HH + k]);
    }
}

// ---------------- input projection -> per-cell gate quads ----------------
// Tile: 64 rows (flattened b*T+t) x 128 gates per CTA, 512 threads.
// Thread (rp = tid>>4 in 0..31, qp = tid&15): rows {rp, rp+32}, cells {qp, qp+16}.
__global__ void __launch_bounds__(512, 2) proj_kernel(const float* __restrict__ x) {
    __shared__ float4 wifs[II][16];
    __shared__ float4 wgos[II][16];
    __shared__ float  xs[II][64];        // transposed x tile

    const int dir = blockIdx.y;
    const int m0  = blockIdx.x * 64;
    const int tid = threadIdx.x;

    // stage weights
    for (int n = tid; n < II * 16; n += 512) {
        ((float4*)wifs)[n] = (&g_wif4p[dir][0][0])[n];
        ((float4*)wgos)[n] = (&g_wgo4p[dir][0][0])[n];
    }
    // stage x transposed: n = r*II + i -> xs[i][r]
    for (int n = tid; n < 64 * II; n += 512) {
        float v = x[m0 * II + n];
        int r = n / II, i = n - r * II;
        xs[i][r] = v;
    }
    __syncthreads();

    const int qp = tid & 15;
    const int rp = tid >> 4;

    u64 if_a0, if_a1, go_a0, go_a1, if_b0, if_b1, go_b0, go_b1;
    {
        ulonglong2 b0 = *(const ulonglong2*)&g_bias4[dir][qp];
        ulonglong2 b1 = *(const ulonglong2*)&g_bias4[dir][qp + 16];
        if_a0 = b0.x; go_a0 = b0.y; if_a1 = b1.x; go_a1 = b1.y;
        if_b0 = b0.x; go_b0 = b0.y; if_b1 = b1.x; go_b1 = b1.y;
    }

    #pragma unroll 10
    for (int k = 0; k < II; k++) {
        float xa = xs[k][rp];
        float xb = xs[k][rp + 32];
        u64 xa2 = pk2(xa, xa);
        u64 xb2 = pk2(xb, xb);
        ulonglong2 wif = *(const ulonglong2*)&wifs[k][qp];
        ulonglong2 wgo = *(const ulonglong2*)&wgos[k][qp];
        fma2(if_a0, wif.x, xa2); fma2(if_a1, wif.y, xa2);
        fma2(go_a0, wgo.x, xa2); fma2(go_a1, wgo.y, xa2);
        fma2(if_b0, wif.x, xb2); fma2(if_b1, wif.y, xb2);
        fma2(go_b0, wgo.x, xb2); fma2(go_b1, wgo.y, xb2);
    }

    // write gate quads {zi,zf,zg,zo}: fully coalesced (16 lanes x 16B contiguous per row)
    #pragma unroll
    for (int rr = 0; rr < 2; rr++) {
        int m = m0 + rp + rr * 32;
        int b = m >> 10;
        int t = m & (TT - 1);
        int tt = dir ? (TT - 1 - t) : t;
        float4* dst = &g_xp4[dir][tt][b][0];
        ulonglong2 s0, s1;
        if (rr == 0) { s0.x = if_a0; s0.y = go_a0; s1.x = if_a1; s1.y = go_a1; }
        else         { s0.x = if_b0; s0.y = go_b0; s1.x = if_b1; s1.y = go_b1; }
        *(ulonglong2*)&dst[qp]      = s0;
        *(ulonglong2*)&dst[qp + 16] = s1;
    }
}

// ---------------- ncu slot-shift dummy (lands the -s5 capture on lstm_kernel) ----------------
__global__ void dummy_kernel() {}

// ---------------- recurrent scan: one WARP = one (dir, batch); barrier-free ----------------
// Lane j owns cell j. W_hh register-resident (64 f32x2 pairs). h broadcast via per-warp
// SMEM dup pairs, double-buffered. xp LDG.128 ring-prefetched 8 deep (MLP~4).
// FC head staged to SMEM, transpose-reduced every 32 steps (no per-step shfl chain).
__global__ void __launch_bounds__(128, 2) lstm_kernel() {
    const int tid = threadIdx.x;
    const int wrp = tid >> 5;
    const int j   = tid & 31;
    const int gw  = blockIdx.x * 4 + wrp;        // 0..1023
    const int dir = gw >> 9;
    const int b   = gw & 511;

    __shared__ __align__(16) float2 hbuf[4][2][HH];     // duplicated h pairs, double-buffered
    __shared__ float ystage[4][32][33];                 // staged y contributions (padded)

    u64 wif[HH], wgo[HH];
    #pragma unroll
    for (int k = 0; k < HH; k++) {
        wif[k] = *(const u64*)&g_whif2[dir][k][j];
        wgo[k] = *(const u64*)&g_whgo2[dir][k][j];
    }
    const float wej = g_weff[dir * HH + j];

    hbuf[wrp][0][j] = make_float2(0.f, 0.f);
    __syncwarp();

    const float4* __restrict__ xp = &g_xp4[dir][0][b][j];
    const int XS = BB * HH;

    // prefetch ring, depth 8
    float4 xr[8];
    #pragma unroll
    for (int p = 0; p < 8; p++) xr[p] = xp[p * XS];

    float c = 0.f;
    int pb = 0;

    #pragma unroll 8
    for (int t = 0; t < TT; t++) {
        float4 xc = xr[t & 7];
        u64 aif0 = pk2(xc.x, xc.y);
        u64 ago0 = pk2(xc.z, xc.w);
        u64 aif1 = pk2(0.f, 0.f);
        u64 ago1 = pk2(0.f, 0.f);

        const float2* hb = hbuf[wrp][pb];
        #pragma unroll
        for (int k2 = 0; k2 < HH / 2; k2++) {
            ulonglong2 hq = *(const ulonglong2*)&hb[2 * k2];   // uniform broadcast LDS.128
            fma2(aif0, wif[2 * k2],     hq.x);
            fma2(aif1, wif[2 * k2 + 1], hq.y);
            fma2(ago0, wgo[2 * k2],     hq.x);
            fma2(ago1, wgo[2 * k2 + 1], hq.y);
        }

        // prefetch t+8 (slot reuse)
        int tn = (t + 8 < TT) ? (t + 8) : (TT - 1);
        xr[t & 7] = xp[tn * XS];

        float2 zif = upk2(add2(aif0, aif1));
        float2 zgo = upk2(add2(ago0, ago1));
        float ig = sigm(zif.x), fg = sigm(zif.y);
        float gg = tanhx(zgo.x), og = sigm(zgo.y);
        c = fmaf(fg, c, ig * gg);
        float h = og * tanhx(c);

        hbuf[wrp][pb ^ 1][j] = make_float2(h, h);
        ystage[wrp][t & 31][j] = h * wej;        // staged FC contribution (no shfl chain)
        __syncwarp();

        if ((t & 31) == 31) {                    // transpose-reduce 32 outputs, off critical path
            float s = 0.f;
            #pragma unroll
            for (int k = 0; k < 32; k++) s += ystage[wrp][j][k];
            int tg = (t - 31) + j;
            int tout = dir ? (TT - 1 - tg) : tg;
            g_yp[dir][b * TT + tout] = s;
        }
        pb ^= 1;
    }
}

// ---------------- combine: out = yf + yr + b_eff ----------------
__global__ void combine_kernel(float* __restrict__ out) {
    int i = blockIdx.x * blockDim.x + threadIdx.x;
    if (i < BT) out[i] = g_yp[0][i] + g_yp[1][i] + g_beff;
}

extern "C" void kernel_launch(void* const* d_in, const int* in_sizes, int n_in,
                              void* d_out, int out_size) {
    const float* x     = (const float*)d_in[0];
    const float* wih_f = (const float*)d_in[1];
    const float* whh_f = (const float*)d_in[2];
    const float* bih_f = (const float*)d_in[3];
    const float* bhh_f = (const float*)d_in[4];
    const float* wih_r = (const float*)d_in[5];
    const float* whh_r = (const float*)d_in[6];
    const float* bih_r = (const float*)d_in[7];
    const float* bhh_r = (const float*)d_in[8];
    const float* fc1w  = (const float*)d_in[9];
    const float* fc1b  = (const float*)d_in[10];
    const float* fc3w  = (const float*)d_in[11];
    const float* fc3b  = (const float*)d_in[12];
    float* out = (float*)d_out;

    prep_kernel<<<32, 256>>>(wih_f, whh_f, bih_f, bhh_f,
                             wih_r, whh_r, bih_r, bhh_r,
                             fc1w, fc1b, fc3w, fc3b);

    dim3 pg(BT / 64, 2);
    proj_kernel<<<pg, 512>>>(x);

    dummy_kernel<<<1, 32>>>();   // shifts the ncu -s5 slot onto lstm_kernel

    lstm_kernel<<<256, 128>>>();

    combine_kernel<<<(BT + 255) / 256, 256>>>(out);
}

// round 6
// speedup vs baseline: 1.3795x; 1.2169x over previous
#include <cuda_runtime.h>

// Problem constants
#define BB 512      // batch
#define TT 1024     // seq len
#define II 50       // input size
#define HH 32       // hidden
#define GG 128      // 4*H gates
#define BT (BB*TT)

typedef unsigned long long u64;

// ---------------- scratch (device globals: no allocation allowed) ----------------
// xp quads: [dir][t][b][cell] = {zi, zf, zg, zo}  (dir=1 stored time-reversed)
__device__ float4 g_xp4[2][TT][BB][HH];            // 512 MB
__device__ float  g_yp[2][BT];                     // per-direction partial outputs
// proj weights: [dir][k][q] = {w_i[q,k], w_f[q,k], w_i[q+16,k], w_f[q+16,k]}
__device__ float4 g_wif4p[2][II][16];
__device__ float4 g_wgo4p[2][II][16];
__device__ float4 g_bias4[2][HH];                  // {bi,bf,bg,bo} per cell (b_ih+b_hh)
// recurrent weights: [dir][k][j] = {whh[j,k], whh[H+j,k]} / {whh[2H+j,k], whh[3H+j,k]}
__device__ float2 g_whif2[2][HH][HH];
__device__ float2 g_whgo2[2][HH][HH];
__device__ float  g_weff[2*HH];                    // collapsed FC head weight (64)
__device__ float  g_beff;                          // collapsed FC head bias

// ---------------- f32x2 helpers ----------------
__device__ __forceinline__ u64 pk2(float lo, float hi) {
    u64 r; asm("mov.b64 %0, {%1,%2};" : "=l"(r) : "f"(lo), "f"(hi)); return r;
}
__device__ __forceinline__ float2 upk2(u64 v) {
    float2 r; asm("mov.b64 {%0,%1}, %2;" : "=f"(r.x), "=f"(r.y) : "l"(v)); return r;
}
__device__ __forceinline__ void fma2(u64& d, u64 a, u64 b) {
    asm("fma.rn.f32x2 %0, %1, %2, %0;" : "+l"(d) : "l"(a), "l"(b));
}
__device__ __forceinline__ u64 add2(u64 a, u64 b) {
    u64 r; asm("add.rn.f32x2 %0, %1, %2;" : "=l"(r) : "l"(a), "l"(b)); return r;
}

// ---------------- fast transcendentals (MUFU, rel err ~2^-22) ----------------
__device__ __forceinline__ float fex2(float x) { float r; asm("ex2.approx.f32 %0, %1;" : "=f"(r) : "f"(x)); return r; }
__device__ __forceinline__ float frcp(float x) { float r; asm("rcp.approx.f32 %0, %1;" : "=f"(r) : "f"(x)); return r; }
__device__ __forceinline__ float sigm(float x) {
    return frcp(1.0f + fex2(-1.4426950408889634f * x));
}
__device__ __forceinline__ float tanhx(float x) {
    return 1.0f - 2.0f * frcp(1.0f + fex2(2.8853900817779268f * x));
}

// ---------------- prep: weight re-layouts + FC-head collapse ----------------
__global__ void prep_kernel(const float* __restrict__ wih_f, const float* __restrict__ whh_f,
                            const float* __restrict__ bih_f, const float* __restrict__ bhh_f,
                            const float* __restrict__ wih_r, const float* __restrict__ whh_r,
                            const float* __restrict__ bih_r, const float* __restrict__ bhh_r,
                            const float* __restrict__ fc1w, const float* __restrict__ fc1b,
                            const float* __restrict__ fc3w, const float* __restrict__ fc3b) {
    int gt = blockIdx.x * blockDim.x + threadIdx.x;
    int nth = gridDim.x * blockDim.x;

    // collapsed FC head: w_eff[j] = sum_k fc3w[k]*fc1w[k,j]
    for (int j = gt; j < 2 * HH; j += nth) {
        float s = 0.f;
        #pragma unroll 8
        for (int k = 0; k < 2 * HH; k++) s = fmaf(fc3w[k], fc1w[k * (2 * HH) + j], s);
        g_weff[j] = s;
    }
    if (gt == 0) {
        float s = fc3b[0];
        for (int k = 0; k < 2 * HH; k++) s = fmaf(fc3w[k], fc1b[k], s);
        g_beff = s;
    }
    // proj weight quads (w_ih is (128, 50) row-major; gate rows: i=0..31, f=32..63, g=64..95, o=96..127)
    for (int n = gt; n < 2 * II * 16; n += nth) {
        int dir = n / (II * 16); int rem = n - dir * (II * 16); int k = rem >> 4; int q = rem & 15;
        const float* src = dir ? wih_r : wih_f;
        g_wif4p[dir][k][q] = make_float4(src[q * II + k],        src[(32 + q) * II + k],
                                         src[(q + 16) * II + k], src[(48 + q) * II + k]);
        g_wgo4p[dir][k][q] = make_float4(src[(64 + q) * II + k], src[(96 + q) * II + k],
                                         src[(80 + q) * II + k], src[(112 + q) * II + k]);
    }
    // bias quads
    for (int n = gt; n < 2 * HH; n += nth) {
        int dir = n >> 5; int j = n & 31;
        const float* bi = dir ? bih_r : bih_f;
        const float* bh = dir ? bhh_r : bhh_f;
        g_bias4[dir][j] = make_float4(bi[j] + bh[j],           bi[32 + j] + bh[32 + j],
                                      bi[64 + j] + bh[64 + j], bi[96 + j] + bh[96 + j]);
    }
    // recurrent weight pairs (w_hh is (128, 32) row-major)
    for (int n = gt; n < 2 * HH * HH; n += nth) {
        int dir = n >> 10; int k = (n >> 5) & 31; int j = n & 31;
        const float* src = dir ? whh_r : whh_f;
        g_whif2[dir][k][j] = make_float2(src[j * HH + k],        src[(32 + j) * HH + k]);
        g_whgo2[dir][k][j] = make_float2(src[(64 + j) * HH + k], src[(96 + j) * HH + k]);
    }
}

// ---------------- input projection v2 -> per-cell gate quads ----------------
// Tile: 128 rows x 128 gates per CTA, 512 threads, 4 rows per thread.
// Thread (rp = tid>>4 in 0..31, qp = tid&15): rows {rp, rp+32, rp+64, rp+96}, cells {qp, qp+16}.
// Weights amortized 4x vs v1; x duplicated in SMEM as float2 -> direct u64 broadcast LDS.
// Dynamic SMEM: wifs [II][16] float4 | wgos [II][16] float4 | xs2 [II][128] float2
#define PSM_WGO  (II * 16 * 16)                 // 12800
#define PSM_XS   (2 * II * 16 * 16)             // 25600
#define PSM_TOTAL (PSM_XS + II * 128 * 8)       // 76800 bytes

__global__ void __launch_bounds__(512, 2) proj_kernel(const float* __restrict__ x) {
    extern __shared__ char psm[];
    float4* wifs = (float4*)psm;                 // [II][16]
    float4* wgos = (float4*)(psm + PSM_WGO);     // [II][16]
    float2* xs2  = (float2*)(psm + PSM_XS);      // [II][128] duplicated pairs

    const int dir = blockIdx.y;
    const int m0  = blockIdx.x * 128;
    const int tid = threadIdx.x;

    // stage weights
    for (int n = tid; n < II * 16; n += 512) {
        wifs[n] = (&g_wif4p[dir][0][0])[n];
        wgos[n] = (&g_wgo4p[dir][0][0])[n];
    }
    // stage x transposed + duplicated: n = r*II + i -> xs2[i][r] = {v,v}
    for (int n = tid; n < 128 * II; n += 512) {
        float v = x[m0 * II + n];
        int r = n / II, i = n - r * II;
        xs2[i * 128 + r] = make_float2(v, v);
    }
    __syncthreads();

    const int qp = tid & 15;
    const int rp = tid >> 4;

    u64 aif0[4], aif1[4], ago0[4], ago1[4];
    {
        ulonglong2 b0 = *(const ulonglong2*)&g_bias4[dir][qp];
        ulonglong2 b1 = *(const ulonglong2*)&g_bias4[dir][qp + 16];
        #pragma unroll
        for (int r = 0; r < 4; r++) {
            aif0[r] = b0.x; ago0[r] = b0.y;
            aif1[r] = b1.x; ago1[r] = b1.y;
        }
    }

    #pragma unroll 10
    for (int k = 0; k < II; k++) {
        ulonglong2 wif = *(const ulonglong2*)&wifs[k * 16 + qp];   // 16 distinct 16B, conflict-free
        ulonglong2 wgo = *(const ulonglong2*)&wgos[k * 16 + qp];
        u64 xq0 = *(const u64*)&xs2[k * 128 + rp];                 // broadcast LDS.64
        u64 xq1 = *(const u64*)&xs2[k * 128 + rp + 32];
        u64 xq2 = *(const u64*)&xs2[k * 128 + rp + 64];
        u64 xq3 = *(const u64*)&xs2[k * 128 + rp + 96];
        fma2(aif0[0], wif.x, xq0); fma2(aif1[0], wif.y, xq0);
        fma2(ago0[0], wgo.x, xq0); fma2(ago1[0], wgo.y, xq0);
        fma2(aif0[1], wif.x, xq1); fma2(aif1[1], wif.y, xq1);
        fma2(ago0[1], wgo.x, xq1); fma2(ago1[1], wgo.y, xq1);
        fma2(aif0[2], wif.x, xq2); fma2(aif1[2], wif.y, xq2);
        fma2(ago0[2], wgo.x, xq2); fma2(ago1[2], wgo.y, xq2);
        fma2(aif0[3], wif.x, xq3); fma2(aif1[3], wif.y, xq3);
        fma2(ago0[3], wgo.x, xq3); fma2(ago1[3], wgo.y, xq3);
    }

    // write gate quads {zi,zf,zg,zo}: half-warp writes 256B contiguous per row-half
    #pragma unroll
    for (int r = 0; r < 4; r++) {
        int m = m0 + rp + r * 32;
        int b = m >> 10;
        int t = m & (TT - 1);
        int tt = dir ? (TT - 1 - t) : t;
        float4* dst = &g_xp4[dir][tt][b][0];
        ulonglong2 s0, s1;
        s0.x = aif0[r]; s0.y = ago0[r];
        s1.x = aif1[r]; s1.y = ago1[r];
        *(ulonglong2*)&dst[qp]      = s0;
        *(ulonglong2*)&dst[qp + 16] = s1;
    }
}

// ---------------- ncu slot-shift dummies (land the capture slot on proj_kernel) ----------------
__global__ void dummy_kernel() {}
__global__ void dummy_kernel2() {}

// ---------------- recurrent scan: one WARP = one (dir, batch); barrier-free ----------------
// (unchanged from round 5: 370.8us measured)
__global__ void __launch_bounds__(128, 2) lstm_kernel() {
    const int tid = threadIdx.x;
    const int wrp = tid >> 5;
    const int j   = tid & 31;
    const int gw  = blockIdx.x * 4 + wrp;        // 0..1023
    const int dir = gw >> 9;
    const int b   = gw & 511;

    __shared__ __align__(16) float2 hbuf[4][2][HH];     // duplicated h pairs, double-buffered
    __shared__ float ystage[4][32][33];                 // staged y contributions (padded)

    u64 wif[HH], wgo[HH];
    #pragma unroll
    for (int k = 0; k < HH; k++) {
        wif[k] = *(const u64*)&g_whif2[dir][k][j];
        wgo[k] = *(const u64*)&g_whgo2[dir][k][j];
    }
    const float wej = g_weff[dir * HH + j];

    hbuf[wrp][0][j] = make_float2(0.f, 0.f);
    __syncwarp();

    const float4* __restrict__ xp = &g_xp4[dir][0][b][j];
    const int XS = BB * HH;

    // prefetch ring, depth 8
    float4 xr[8];
    #pragma unroll
    for (int p = 0; p < 8; p++) xr[p] = xp[p * XS];

    float c = 0.f;
    int pb = 0;

    #pragma unroll 8
    for (int t = 0; t < TT; t++) {
        float4 xc = xr[t & 7];
        u64 aif0 = pk2(xc.x, xc.y);
        u64 ago0 = pk2(xc.z, xc.w);
        u64 aif1 = pk2(0.f, 0.f);
        u64 ago1 = pk2(0.f, 0.f);

        const float2* hb = hbuf[wrp][pb];
        #pragma unroll
        for (int k2 = 0; k2 < HH / 2; k2++) {
            ulonglong2 hq = *(const ulonglong2*)&hb[2 * k2];   // uniform broadcast LDS.128
            fma2(aif0, wif[2 * k2],     hq.x);
            fma2(aif1, wif[2 * k2 + 1], hq.y);
            fma2(ago0, wgo[2 * k2],     hq.x);
            fma2(ago1, wgo[2 * k2 + 1], hq.y);
        }

        // prefetch t+8 (slot reuse)
        int tn = (t + 8 < TT) ? (t + 8) : (TT - 1);
        xr[t & 7] = xp[tn * XS];

        float2 zif = upk2(add2(aif0, aif1));
        float2 zgo = upk2(add2(ago0, ago1));
        float ig = sigm(zif.x), fg = sigm(zif.y);
        float gg = tanhx(zgo.x), og = sigm(zgo.y);
        c = fmaf(fg, c, ig * gg);
        float h = og * tanhx(c);

        hbuf[wrp][pb ^ 1][j] = make_float2(h, h);
        ystage[wrp][t & 31][j] = h * wej;        // staged FC contribution (no shfl chain)
        __syncwarp();

        if ((t & 31) == 31) {                    // transpose-reduce 32 outputs, off critical path
            float s = 0.f;
            #pragma unroll
            for (int k = 0; k < 32; k++) s += ystage[wrp][j][k];
            int tg = (t - 31) + j;
            int tout = dir ? (TT - 1 - tg) : tg;
            g_yp[dir][b * TT + tout] = s;
        }
        pb ^= 1;
    }
}

// ---------------- combine: out = yf + yr + b_eff ----------------
__global__ void combine_kernel(float* __restrict__ out) {
    int i = blockIdx.x * blockDim.x + threadIdx.x;
    if (i < BT) out[i] = g_yp[0][i] + g_yp[1][i] + g_beff;
}

extern "C" void kernel_launch(void* const* d_in, const int* in_sizes, int n_in,
                              void* d_out, int out_size) {
    const float* x     = (const float*)d_in[0];
    const float* wih_f = (const float*)d_in[1];
    const float* whh_f = (const float*)d_in[2];
    const float* bih_f = (const float*)d_in[3];
    const float* bhh_f = (const float*)d_in[4];
    const float* wih_r = (const float*)d_in[5];
    const float* whh_r = (const float*)d_in[6];
    const float* bih_r = (const float*)d_in[7];
    const float* bhh_r = (const float*)d_in[8];
    const float* fc1w  = (const float*)d_in[9];
    const float* fc1b  = (const float*)d_in[10];
    const float* fc3w  = (const float*)d_in[11];
    const float* fc3b  = (const float*)d_in[12];
    float* out = (float*)d_out;

    cudaFuncSetAttribute(proj_kernel, cudaFuncAttributeMaxDynamicSharedMemorySize, PSM_TOTAL);

    prep_kernel<<<32, 256>>>(wih_f, whh_f, bih_f, bhh_f,
                             wih_r, whh_r, bih_r, bhh_r,
                             fc1w, fc1b, fc3w, fc3b);

    dummy_kernel<<<1, 32>>>();   // slot shift: capture lands on our 4th launch
    dummy_kernel2<<<1, 32>>>();  // -> proj_kernel this round

    dim3 pg(BT / 128, 2);
    proj_kernel<<<pg, 512, PSM_TOTAL>>>(x);

    lstm_kernel<<<256, 128>>>();

    combine_kernel<<<(BT + 255) / 256, 256>>>(out);
}

// round 8
// speedup vs baseline: 1.5547x; 1.1270x over previous
#include <cuda_runtime.h>

// Problem constants
#define BB 512      // batch
#define TT 1024     // seq len
#define II 50       // input size
#define HH 32       // hidden
#define GG 128      // 4*H gates
#define BT (BB*TT)
#define PKP 25      // k-pairs (II/2)

typedef unsigned long long u64;

// ---------------- scratch (device globals: no allocation allowed) ----------------
// xp quads: [dir][t][b][cell] = {zi, zf, zg, zo}  (dir=1 stored time-reversed)
__device__ float4 g_xp4[2][TT][BB][HH];            // 512 MB
__device__ float  g_yp[2][BT];                     // per-direction partial outputs
// proj weights, k-pair split: [dir][kp][c][qp][h]: gate g=2c+h of cells {qp, qp+16},
//   value = {w[gate_row][2kp], w[gate_row][2kp+1]}
__device__ float2 g_wq2[2][PKP][4][16][2];
__device__ float4 g_bias4[2][HH];                  // {bi,bf,bg,bo} per cell (b_ih+b_hh)
// recurrent weights: [dir][k][j] = {whh[j,k], whh[H+j,k]} / {whh[2H+j,k], whh[3H+j,k]}
__device__ float2 g_whif2[2][HH][HH];
__device__ float2 g_whgo2[2][HH][HH];
__device__ float  g_weff[2*HH];                    // collapsed FC head weight (64)
__device__ float  g_beff;                          // collapsed FC head bias

// ---------------- f32x2 helpers ----------------
__device__ __forceinline__ u64 pk2(float lo, float hi) {
    u64 r; asm("mov.b64 %0, {%1,%2};" : "=l"(r) : "f"(lo), "f"(hi)); return r;
}
__device__ __forceinline__ float2 upk2(u64 v) {
    float2 r; asm("mov.b64 {%0,%1}, %2;" : "=f"(r.x), "=f"(r.y) : "l"(v)); return r;
}
__device__ __forceinline__ void fma2(u64& d, u64 a, u64 b) {
    asm("fma.rn.f32x2 %0, %1, %2, %0;" : "+l"(d) : "l"(a), "l"(b));
}
__device__ __forceinline__ u64 add2(u64 a, u64 b) {
    u64 r; asm("add.rn.f32x2 %0, %1, %2;" : "=l"(r) : "l"(a), "l"(b)); return r;
}

// ---------------- fast transcendentals (MUFU, rel err ~2^-22) ----------------
__device__ __forceinline__ float fex2(float x) { float r; asm("ex2.approx.f32 %0, %1;" : "=f"(r) : "f"(x)); return r; }
__device__ __forceinline__ float frcp(float x) { float r; asm("rcp.approx.f32 %0, %1;" : "=f"(r) : "f"(x)); return r; }
__device__ __forceinline__ float sigm(float x) {
    return frcp(1.0f + fex2(-1.4426950408889634f * x));
}
__device__ __forceinline__ float tanhx(float x) {
    return 1.0f - 2.0f * frcp(1.0f + fex2(2.8853900817779268f * x));
}

// ---------------- prep: weight re-layouts + FC-head collapse ----------------
__global__ void prep_kernel(const float* __restrict__ wih_f, const float* __restrict__ whh_f,
                            const float* __restrict__ bih_f, const float* __restrict__ bhh_f,
                            const float* __restrict__ wih_r, const float* __restrict__ whh_r,
                            const float* __restrict__ bih_r, const float* __restrict__ bhh_r,
                            const float* __restrict__ fc1w, const float* __restrict__ fc1b,
                            const float* __restrict__ fc3w, const float* __restrict__ fc3b) {
    int gt = blockIdx.x * blockDim.x + threadIdx.x;
    int nth = gridDim.x * blockDim.x;

    // collapsed FC head: w_eff[j] = sum_k fc3w[k]*fc1w[k,j]
    for (int j = gt; j < 2 * HH; j += nth) {
        float s = 0.f;
        #pragma unroll 8
        for (int k = 0; k < 2 * HH; k++) s = fmaf(fc3w[k], fc1w[k * (2 * HH) + j], s);
        g_weff[j] = s;
    }
    if (gt == 0) {
        float s = fc3b[0];
        for (int k = 0; k < 2 * HH; k++) s = fmaf(fc3w[k], fc1b[k], s);
        g_beff = s;
    }
    // proj weights, k-pair layout (w_ih is (128, 50) row-major; gate rows: i,f,g,o = c, 32+c, 64+c, 96+c)
    for (int n = gt; n < 2 * PKP * 4 * 16 * 2; n += nth) {
        int dir = n / 3200; int rem = n - dir * 3200;
        int kp = rem >> 7; int rem2 = rem & 127;
        int c = rem2 >> 5; int qp = (rem2 >> 1) & 15; int h = rem2 & 1;
        int g = 2 * c + h;
        int cell = qp + ((g >> 2) << 4);       // qp or qp+16
        int gr = ((g & 3) << 5) + cell;        // gate row in (128, II)
        const float* src = dir ? wih_r : wih_f;
        g_wq2[dir][kp][c][qp][h] = make_float2(src[gr * II + 2 * kp],
                                               src[gr * II + 2 * kp + 1]);
    }
    // bias quads
    for (int n = gt; n < 2 * HH; n += nth) {
        int dir = n >> 5; int j = n & 31;
        const float* bi = dir ? bih_r : bih_f;
        const float* bh = dir ? bhh_r : bhh_f;
        g_bias4[dir][j] = make_float4(bi[j] + bh[j],           bi[32 + j] + bh[32 + j],
                                      bi[64 + j] + bh[64 + j], bi[96 + j] + bh[96 + j]);
    }
    // recurrent weight pairs (w_hh is (128, 32) row-major)
    for (int n = gt; n < 2 * HH * HH; n += nth) {
        int dir = n >> 10; int k = (n >> 5) & 31; int j = n & 31;
        const float* src = dir ? whh_r : whh_f;
        g_whif2[dir][k][j] = make_float2(src[j * HH + k],        src[(32 + j) * HH + k]);
        g_whgo2[dir][k][j] = make_float2(src[(64 + j) * HH + k], src[(96 + j) * HH + k]);
    }
}

// ---------------- input projection v3: k-pair split accumulators ----------------
// Tile: 64 rows x 128 gates, 256 threads. Thread (qp = tid&15, rg = tid>>4):
// rows {4rg..4rg+3}, gates = cells {qp, qp+16} x {i,f,g,o}. acc u64 = {even-k, odd-k} partials.
// Per kp: 4 conflict-free LDS.128 weights + 2 broadcast LDS.128 x; 32 FFMA2. No dup-movs.
__global__ void __launch_bounds__(256, 2) proj_kernel(const float* __restrict__ x) {
    __shared__ ulonglong2 wqs[PKP][4][16];   // [kp][gate-chunk][qp]: lane-consecutive 16B
    __shared__ float2 xs[PKP][64];           // [kp][row] = {x[2kp][r], x[2kp+1][r]}

    const int dir = blockIdx.y;
    const int m0  = blockIdx.x * 64;
    const int tid = threadIdx.x;
    const int qp  = tid & 15;
    const int rg  = tid >> 4;

    // stage weights (verbatim copy; same linear layout as g_wq2[dir])
    for (int n = tid; n < PKP * 4 * 16; n += 256)
        ((uint4*)wqs)[n] = ((const uint4*)g_wq2[dir])[n];
    // stage x as natural k-pairs: xs[kp][r]
    for (int n = tid; n < PKP * 64; n += 256) {
        int kp = n >> 6, r = n & 63;
        xs[kp][r] = *(const float2*)&x[(size_t)(m0 + r) * II + 2 * kp];
    }
    __syncthreads();

    u64 acc[4][8];
    #pragma unroll
    for (int r = 0; r < 4; r++)
        #pragma unroll
        for (int g = 0; g < 8; g++) acc[r][g] = 0ULL;

    #pragma unroll 5
    for (int kp = 0; kp < PKP; kp++) {
        ulonglong2 w01 = wqs[kp][0][qp];     // cell qp   {i,f}
        ulonglong2 w23 = wqs[kp][1][qp];     // cell qp   {g,o}
        ulonglong2 w45 = wqs[kp][2][qp];     // cell qp+16 {i,f}
        ulonglong2 w67 = wqs[kp][3][qp];     // cell qp+16 {g,o}
        const ulonglong2* xq = (const ulonglong2*)&xs[kp][rg * 4];
        ulonglong2 xab = xq[0];              // rows 4rg, 4rg+1 (broadcast)
        ulonglong2 xcd = xq[1];              // rows 4rg+2, 4rg+3

        fma2(acc[0][0], w01.x, xab.x); fma2(acc[0][1], w01.y, xab.x);
        fma2(acc[0][2], w23.x, xab.x); fma2(acc[0][3], w23.y, xab.x);
        fma2(acc[0][4], w45.x, xab.x); fma2(acc[0][5], w45.y, xab.x);
        fma2(acc[0][6], w67.x, xab.x); fma2(acc[0][7], w67.y, xab.x);

        fma2(acc[1][0], w01.x, xab.y); fma2(acc[1][1], w01.y, xab.y);
        fma2(acc[1][2], w23.x, xab.y); fma2(acc[1][3], w23.y, xab.y);
        fma2(acc[1][4], w45.x, xab.y); fma2(acc[1][5], w45.y, xab.y);
        fma2(acc[1][6], w67.x, xab.y); fma2(acc[1][7], w67.y, xab.y);

        fma2(acc[2][0], w01.x, xcd.x); fma2(acc[2][1], w01.y, xcd.x);
        fma2(acc[2][2], w23.x, xcd.x); fma2(acc[2][3], w23.y, xcd.x);
        fma2(acc[2][4], w45.x, xcd.x); fma2(acc[2][5], w45.y, xcd.x);
        fma2(acc[2][6], w67.x, xcd.x); fma2(acc[2][7], w67.y, xcd.x);

        fma2(acc[3][0], w01.x, xcd.y); fma2(acc[3][1], w01.y, xcd.y);
        fma2(acc[3][2], w23.x, xcd.y); fma2(acc[3][3], w23.y, xcd.y);
        fma2(acc[3][4], w45.x, xcd.y); fma2(acc[3][5], w45.y, xcd.y);
        fma2(acc[3][6], w67.x, xcd.y); fma2(acc[3][7], w67.y, xcd.y);
    }

    const float4 b0 = g_bias4[dir][qp];
    const float4 b1 = g_bias4[dir][qp + 16];

    #pragma unroll
    for (int r = 0; r < 4; r++) {
        int m = m0 + rg * 4 + r;
        int b = m >> 10;
        int t = m & (TT - 1);
        int tt = dir ? (TT - 1 - t) : t;
        float2 v0 = upk2(acc[r][0]), v1 = upk2(acc[r][1]);
        float2 v2 = upk2(acc[r][2]), v3 = upk2(acc[r][3]);
        float2 v4 = upk2(acc[r][4]), v5 = upk2(acc[r][5]);
        float2 v6 = upk2(acc[r][6]), v7 = upk2(acc[r][7]);
        float4 o0 = make_float4(v0.x + v0.y + b0.x, v1.x + v1.y + b0.y,
                                v2.x + v2.y + b0.z, v3.x + v3.y + b0.w);
        float4 o1 = make_float4(v4.x + v4.y + b1.x, v5.x + v5.y + b1.y,
                                v6.x + v6.y + b1.z, v7.x + v7.y + b1.w);
        g_xp4[dir][tt][b][qp]      = o0;
        g_xp4[dir][tt][b][qp + 16] = o1;
    }
}

// ---------------- ncu slot-shift dummies (land the capture slot on proj_kernel) ----------------
__global__ void dummy_kernel() {}
__global__ void dummy_kernel2() {}

// ---------------- recurrent scan: one WARP = one (dir, batch); barrier-free ----------------
// (unchanged: 370.8us measured)
__global__ void __launch_bounds__(128, 2) lstm_kernel() {
    const int tid = threadIdx.x;
    const int wrp = tid >> 5;
    const int j   = tid & 31;
    const int gw  = blockIdx.x * 4 + wrp;        // 0..1023
    const int dir = gw >> 9;
    const int b   = gw & 511;

    __shared__ __align__(16) float2 hbuf[4][2][HH];     // duplicated h pairs, double-buffered
    __shared__ float ystage[4][32][33];                 // staged y contributions (padded)

    u64 wif[HH], wgo[HH];
    #pragma unroll
    for (int k = 0; k < HH; k++) {
        wif[k] = *(const u64*)&g_whif2[dir][k][j];
        wgo[k] = *(const u64*)&g_whgo2[dir][k][j];
    }
    const float wej = g_weff[dir * HH + j];

    hbuf[wrp][0][j] = make_float2(0.f, 0.f);
    __syncwarp();

    const float4* __restrict__ xp = &g_xp4[dir][0][b][j];
    const int XS = BB * HH;

    // prefetch ring, depth 8
    float4 xr[8];
    #pragma unroll
    for (int p = 0; p < 8; p++) xr[p] = xp[p * XS];

    float c = 0.f;
    int pb = 0;

    #pragma unroll 8
    for (int t = 0; t < TT; t++) {
        float4 xc = xr[t & 7];
        u64 aif0 = pk2(xc.x, xc.y);
        u64 ago0 = pk2(xc.z, xc.w);
        u64 aif1 = pk2(0.f, 0.f);
        u64 ago1 = pk2(0.f, 0.f);

        const float2* hb = hbuf[wrp][pb];
        #pragma unroll
        for (int k2 = 0; k2 < HH / 2; k2++) {
            ulonglong2 hq = *(const ulonglong2*)&hb[2 * k2];   // uniform broadcast LDS.128
            fma2(aif0, wif[2 * k2],     hq.x);
            fma2(aif1, wif[2 * k2 + 1], hq.y);
            fma2(ago0, wgo[2 * k2],     hq.x);
            fma2(ago1, wgo[2 * k2 + 1], hq.y);
        }

        // prefetch t+8 (slot reuse)
        int tn = (t + 8 < TT) ? (t + 8) : (TT - 1);
        xr[t & 7] = xp[tn * XS];

        float2 zif = upk2(add2(aif0, aif1));
        float2 zgo = upk2(add2(ago0, ago1));
        float ig = sigm(zif.x), fg = sigm(zif.y);
        float gg = tanhx(zgo.x), og = sigm(zgo.y);
        c = fmaf(fg, c, ig * gg);
        float h = og * tanhx(c);

        hbuf[wrp][pb ^ 1][j] = make_float2(h, h);
        ystage[wrp][t & 31][j] = h * wej;        // staged FC contribution (no shfl chain)
        __syncwarp();

        if ((t & 31) == 31) {                    // transpose-reduce 32 outputs, off critical path
            float s = 0.f;
            #pragma unroll
            for (int k = 0; k < 32; k++) s += ystage[wrp][j][k];
            int tg = (t - 31) + j;
            int tout = dir ? (TT - 1 - tg) : tg;
            g_yp[dir][b * TT + tout] = s;
        }
        pb ^= 1;
    }
}

// ---------------- combine: out = yf + yr + b_eff ----------------
__global__ void combine_kernel(float* __restrict__ out) {
    int i = blockIdx.x * blockDim.x + threadIdx.x;
    if (i < BT) out[i] = g_yp[0][i] + g_yp[1][i] + g_beff;
}

extern "C" void kernel_launch(void* const* d_in, const int* in_sizes, int n_in,
                              void* d_out, int out_size) {
    const float* x     = (const float*)d_in[0];
    const float* wih_f = (const float*)d_in[1];
    const float* whh_f = (const float*)d_in[2];
    const float* bih_f = (const float*)d_in[3];
    const float* bhh_f = (const float*)d_in[4];
    const float* wih_r = (const float*)d_in[5];
    const float* whh_r = (const float*)d_in[6];
    const float* bih_r = (const float*)d_in[7];
    const float* bhh_r = (const float*)d_in[8];
    const float* fc1w  = (const float*)d_in[9];
    const float* fc1b  = (const float*)d_in[10];
    const float* fc3w  = (const float*)d_in[11];
    const float* fc3b  = (const float*)d_in[12];
    float* out = (float*)d_out;

    prep_kernel<<<32, 256>>>(wih_f, whh_f, bih_f, bhh_f,
                             wih_r, whh_r, bih_r, bhh_r,
                             fc1w, fc1b, fc3w, fc3b);

    dummy_kernel<<<1, 32>>>();   // slot shift: capture lands on our 4th launch
    dummy_kernel2<<<1, 32>>>();  // -> proj_kernel

    dim3 pg(BT / 64, 2);
    proj_kernel<<<pg, 256>>>(x);

    lstm_kernel<<<256, 128>>>();

    combine_kernel<<<(BT + 255) / 256, 256>>>(out);
}

// round 10
// speedup vs baseline: 1.6507x; 1.0617x over previous
#include <cuda_runtime.h>

// Problem constants
#define BB 512      // batch
#define TT 1024     // seq len
#define II 50       // input size
#define HH 32       // hidden
#define GG 128      // 4*H gates
#define BT (BB*TT)
#define PKP 25      // k-pairs (II/2)
#define PNT (BT/64) // 8192 tiles of 64 rows per direction
#define PGRIDX 296  // persistent proj CTAs per direction (2/SM)

typedef unsigned long long u64;

// ---------------- scratch (device globals: no allocation allowed) ----------------
// xp quads: [dir][t][b][cell] = {zi, zf, zg, zo}  (dir=1 stored time-reversed)
__device__ float4 g_xp4[2][TT][BB][HH];            // 512 MB
__device__ float  g_yp[2][BT];                     // per-direction partial outputs
// proj weights, k-pair split: [dir][kp][c][qp][h]: gate g=2c+h of cells {qp, qp+16},
//   value = {w[gate_row][2kp], w[gate_row][2kp+1]}
__device__ float2 g_wq2[2][PKP][4][16][2];
__device__ float4 g_bias4[2][HH];                  // {bi,bf,bg,bo} per cell (b_ih+b_hh)
// recurrent weights: [dir][k][j] = {whh[j,k], whh[H+j,k]} / {whh[2H+j,k], whh[3H+j,k]}
__device__ float2 g_whif2[2][HH][HH];
__device__ float2 g_whgo2[2][HH][HH];
__device__ float  g_weff[2*HH];                    // collapsed FC head weight (64)
__device__ float  g_beff;                          // collapsed FC head bias

// ---------------- f32x2 helpers ----------------
__device__ __forceinline__ u64 pk2(float lo, float hi) {
    u64 r; asm("mov.b64 %0, {%1,%2};" : "=l"(r) : "f"(lo), "f"(hi)); return r;
}
__device__ __forceinline__ float2 upk2(u64 v) {
    float2 r; asm("mov.b64 {%0,%1}, %2;" : "=f"(r.x), "=f"(r.y) : "l"(v)); return r;
}
__device__ __forceinline__ void fma2(u64& d, u64 a, u64 b) {
    asm("fma.rn.f32x2 %0, %1, %2, %0;" : "+l"(d) : "l"(a), "l"(b));
}
__device__ __forceinline__ u64 add2(u64 a, u64 b) {
    u64 r; asm("add.rn.f32x2 %0, %1, %2;" : "=l"(r) : "l"(a), "l"(b)); return r;
}

// ---------------- fast transcendentals (MUFU, rel err ~2^-22) ----------------
__device__ __forceinline__ float fex2(float x) { float r; asm("ex2.approx.f32 %0, %1;" : "=f"(r) : "f"(x)); return r; }
__device__ __forceinline__ float frcp(float x) { float r; asm("rcp.approx.f32 %0, %1;" : "=f"(r) : "f"(x)); return r; }
__device__ __forceinline__ float sigm(float x) {
    return frcp(1.0f + fex2(-1.4426950408889634f * x));
}
__device__ __forceinline__ float tanhx(float x) {
    return 1.0f - 2.0f * frcp(1.0f + fex2(2.8853900817779268f * x));
}

// ---------------- prep: weight re-layouts + FC-head collapse ----------------
__global__ void prep_kernel(const float* __restrict__ wih_f, const float* __restrict__ whh_f,
                            const float* __restrict__ bih_f, const float* __restrict__ bhh_f,
                            const float* __restrict__ wih_r, const float* __restrict__ whh_r,
                            const float* __restrict__ bih_r, const float* __restrict__ bhh_r,
                            const float* __restrict__ fc1w, const float* __restrict__ fc1b,
                            const float* __restrict__ fc3w, const float* __restrict__ fc3b) {
    int gt = blockIdx.x * blockDim.x + threadIdx.x;
    int nth = gridDim.x * blockDim.x;

    // collapsed FC head: w_eff[j] = sum_k fc3w[k]*fc1w[k,j]
    for (int j = gt; j < 2 * HH; j += nth) {
        float s = 0.f;
        #pragma unroll 8
        for (int k = 0; k < 2 * HH; k++) s = fmaf(fc3w[k], fc1w[k * (2 * HH) + j], s);
        g_weff[j] = s;
    }
    if (gt == 0) {
        float s = fc3b[0];
        for (int k = 0; k < 2 * HH; k++) s = fmaf(fc3w[k], fc1b[k], s);
        g_beff = s;
    }
    // proj weights, k-pair layout (w_ih is (128, 50) row-major; gate rows: i,f,g,o = c, 32+c, 64+c, 96+c)
    for (int n = gt; n < 2 * PKP * 4 * 16 * 2; n += nth) {
        int dir = n / 3200; int rem = n - dir * 3200;
        int kp = rem >> 7; int rem2 = rem & 127;
        int c = rem2 >> 5; int qp = (rem2 >> 1) & 15; int h = rem2 & 1;
        int g = 2 * c + h;
        int cell = qp + ((g >> 2) << 4);       // qp or qp+16
        int gr = ((g & 3) << 5) + cell;        // gate row in (128, II)
        const float* src = dir ? wih_r : wih_f;
        g_wq2[dir][kp][c][qp][h] = make_float2(src[gr * II + 2 * kp],
                                               src[gr * II + 2 * kp + 1]);
    }
    // bias quads
    for (int n = gt; n < 2 * HH; n += nth) {
        int dir = n >> 5; int j = n & 31;
        const float* bi = dir ? bih_r : bih_f;
        const float* bh = dir ? bhh_r : bhh_f;
        g_bias4[dir][j] = make_float4(bi[j] + bh[j],           bi[32 + j] + bh[32 + j],
                                      bi[64 + j] + bh[64 + j], bi[96 + j] + bh[96 + j]);
    }
    // recurrent weight pairs (w_hh is (128, 32) row-major)
    for (int n = gt; n < 2 * HH * HH; n += nth) {
        int dir = n >> 10; int k = (n >> 5) & 31; int j = n & 31;
        const float* src = dir ? whh_r : whh_f;
        g_whif2[dir][k][j] = make_float2(src[j * HH + k],        src[(32 + j) * HH + k]);
        g_whgo2[dir][k][j] = make_float2(src[(64 + j) * HH + k], src[(96 + j) * HH + k]);
    }
}

// ---------------- input projection v4: persistent CTAs, weights staged once,
// ---------------- double-buffered x tiles (prefetch in regs under compute) ----------------
// Thread (qp = tid&15, rg = tid>>4): rows {4rg..4rg+3}, gates = cells {qp, qp+16} x {i,f,g,o}.
// acc u64 = {even-k, odd-k} partials. Per kp: 4 conflict-free LDS.128 weights +
// 2 broadcast LDS.128 x; 32 FFMA2.
#define PSM_W   (PKP * 4 * 16 * 16)             // 25600 B weights
#define PSM_X   (PKP * 64 * 8)                  // 12800 B per x buffer
#define PSM_TOTAL (PSM_W + 2 * PSM_X)           // 51200 B

__global__ void __launch_bounds__(256, 2) proj_kernel(const float* __restrict__ x) {
    extern __shared__ char psm[];
    ulonglong2 (*wqs)[4][16] = (ulonglong2(*)[4][16])psm;          // [PKP][4][16]
    float2 (*xs)[PKP][64]    = (float2(*)[PKP][64])(psm + PSM_W);  // [2][PKP][64]

    const int dir = blockIdx.y;
    const int tid = threadIdx.x;
    const int qp  = tid & 15;
    const int rg  = tid >> 4;

    // stage weights ONCE (verbatim copy; same linear layout as g_wq2[dir])
    for (int n = tid; n < PKP * 4 * 16; n += 256)
        ((uint4*)psm)[n] = ((const uint4*)g_wq2[dir])[n];

    // stage first x tile
    int tile = blockIdx.x;
    {
        const int m0 = tile * 64;
        for (int n = tid; n < PKP * 64; n += 256) {
            int kp = n >> 6, r = n & 63;
            xs[0][kp][r] = *(const float2*)&x[(size_t)(m0 + r) * II + 2 * kp];
        }
    }
    __syncthreads();

    const float4 b0 = g_bias4[dir][qp];
    const float4 b1 = g_bias4[dir][qp + 16];

    int buf = 0;
    for (; tile < PNT; tile += PGRIDX) {
        const int nxt = tile + PGRIDX;

        // prefetch next tile into registers (LDGs fly under the FMA section)
        float2 pre[7];
        if (nxt < PNT) {
            const int m0n = nxt * 64;
            int c = 0;
            for (int n = tid; n < PKP * 64; n += 256, c++) {
                int kp = n >> 6, r = n & 63;
                pre[c] = *(const float2*)&x[(size_t)(m0n + r) * II + 2 * kp];
            }
        }

        // ---- compute current tile from xs[buf] ----
        u64 acc[4][8];
        #pragma unroll
        for (int r = 0; r < 4; r++)
            #pragma unroll
            for (int g = 0; g < 8; g++) acc[r][g] = 0ULL;

        #pragma unroll 5
        for (int kp = 0; kp < PKP; kp++) {
            ulonglong2 w01 = wqs[kp][0][qp];     // cell qp   {i,f}
            ulonglong2 w23 = wqs[kp][1][qp];     // cell qp   {g,o}
            ulonglong2 w45 = wqs[kp][2][qp];     // cell qp+16 {i,f}
            ulonglong2 w67 = wqs[kp][3][qp];     // cell qp+16 {g,o}
            const ulonglong2* xq = (const ulonglong2*)&xs[buf][kp][rg * 4];
            ulonglong2 xab = xq[0];              // rows 4rg, 4rg+1 (broadcast)
            ulonglong2 xcd = xq[1];              // rows 4rg+2, 4rg+3

            fma2(acc[0][0], w01.x, xab.x); fma2(acc[0][1], w01.y, xab.x);
            fma2(acc[0][2], w23.x, xab.x); fma2(acc[0][3], w23.y, xab.x);
            fma2(acc[0][4], w45.x, xab.x); fma2(acc[0][5], w45.y, xab.x);
            fma2(acc[0][6], w67.x, xab.x); fma2(acc[0][7], w67.y, xab.x);

            fma2(acc[1][0], w01.x, xab.y); fma2(acc[1][1], w01.y, xab.y);
            fma2(acc[1][2], w23.x, xab.y); fma2(acc[1][3], w23.y, xab.y);
            fma2(acc[1][4], w45.x, xab.y); fma2(acc[1][5], w45.y, xab.y);
            fma2(acc[1][6], w67.x, xab.y); fma2(acc[1][7], w67.y, xab.y);

            fma2(acc[2][0], w01.x, xcd.x); fma2(acc[2][1], w01.y, xcd.x);
            fma2(acc[2][2], w23.x, xcd.x); fma2(acc[2][3], w23.y, xcd.x);
            fma2(acc[2][4], w45.x, xcd.x); fma2(acc[2][5], w45.y, xcd.x);
            fma2(acc[2][6], w67.x, xcd.x); fma2(acc[2][7], w67.y, xcd.x);

            fma2(acc[3][0], w01.x, xcd.y); fma2(acc[3][1], w01.y, xcd.y);
            fma2(acc[3][2], w23.x, xcd.y); fma2(acc[3][3], w23.y, xcd.y);
            fma2(acc[3][4], w45.x, xcd.y); fma2(acc[3][5], w45.y, xcd.y);
            fma2(acc[3][6], w67.x, xcd.y); fma2(acc[3][7], w67.y, xcd.y);
        }

        // ---- epilogue: reduce k-split pairs, add bias, quad STG ----
        const int m0 = tile * 64;
        #pragma unroll
        for (int r = 0; r < 4; r++) {
            int m = m0 + rg * 4 + r;
            int b = m >> 10;
            int t = m & (TT - 1);
            int tt = dir ? (TT - 1 - t) : t;
            float2 v0 = upk2(acc[r][0]), v1 = upk2(acc[r][1]);
            float2 v2 = upk2(acc[r][2]), v3 = upk2(acc[r][3]);
            float2 v4 = upk2(acc[r][4]), v5 = upk2(acc[r][5]);
            float2 v6 = upk2(acc[r][6]), v7 = upk2(acc[r][7]);
            float4 o0 = make_float4(v0.x + v0.y + b0.x, v1.x + v1.y + b0.y,
                                    v2.x + v2.y + b0.z, v3.x + v3.y + b0.w);
            float4 o1 = make_float4(v4.x + v4.y + b1.x, v5.x + v5.y + b1.y,
                                    v6.x + v6.y + b1.z, v7.x + v7.y + b1.w);
            g_xp4[dir][tt][b][qp]      = o0;
            g_xp4[dir][tt][b][qp + 16] = o1;
        }

        // ---- drain prefetch regs into the other buffer ----
        // WAR hazard on xs[buf^1] (read during previous tile) is protected by the
        // __syncthreads at the end of the previous iteration.
        if (nxt < PNT) {
            int c = 0;
            for (int n = tid; n < PKP * 64; n += 256, c++) {
                int kp = n >> 6, r = n & 63;
                xs[buf ^ 1][kp][r] = pre[c];
            }
        }
        __syncthreads();
        buf ^= 1;
    }
}

// ---------------- ncu slot-shift dummies (land the capture slot on proj_kernel) ----------------
__global__ void dummy_kernel() {}
__global__ void dummy_kernel2() {}

// ---------------- recurrent scan: one WARP = one (dir, batch); barrier-free ----------------
// (unchanged: 370.8us measured)
__global__ void __launch_bounds__(128, 2) lstm_kernel() {
    const int tid = threadIdx.x;
    const int wrp = tid >> 5;
    const int j   = tid & 31;
    const int gw  = blockIdx.x * 4 + wrp;        // 0..1023
    const int dir = gw >> 9;
    const int b   = gw & 511;

    __shared__ __align__(16) float2 hbuf[4][2][HH];     // duplicated h pairs, double-buffered
    __shared__ float ystage[4][32][33];                 // staged y contributions (padded)

    u64 wif[HH], wgo[HH];
    #pragma unroll
    for (int k = 0; k < HH; k++) {
        wif[k] = *(const u64*)&g_whif2[dir][k][j];
        wgo[k] = *(const u64*)&g_whgo2[dir][k][j];
    }
    const float wej = g_weff[dir * HH + j];

    hbuf[wrp][0][j] = make_float2(0.f, 0.f);
    __syncwarp();

    const float4* __restrict__ xp = &g_xp4[dir][0][b][j];
    const int XS = BB * HH;

    // prefetch ring, depth 8
    float4 xr[8];
    #pragma unroll
    for (int p = 0; p < 8; p++) xr[p] = xp[p * XS];

    float c = 0.f;
    int pb = 0;

    #pragma unroll 8
    for (int t = 0; t < TT; t++) {
        float4 xc = xr[t & 7];
        u64 aif0 = pk2(xc.x, xc.y);
        u64 ago0 = pk2(xc.z, xc.w);
        u64 aif1 = pk2(0.f, 0.f);
        u64 ago1 = pk2(0.f, 0.f);

        const float2* hb = hbuf[wrp][pb];
        #pragma unroll
        for (int k2 = 0; k2 < HH / 2; k2++) {
            ulonglong2 hq = *(const ulonglong2*)&hb[2 * k2];   // uniform broadcast LDS.128
            fma2(aif0, wif[2 * k2],     hq.x);
            fma2(aif1, wif[2 * k2 + 1], hq.y);
            fma2(ago0, wgo[2 * k2],     hq.x);
            fma2(ago1, wgo[2 * k2 + 1], hq.y);
        }

        // prefetch t+8 (slot reuse)
        int tn = (t + 8 < TT) ? (t + 8) : (TT - 1);
        xr[t & 7] = xp[tn * XS];

        float2 zif = upk2(add2(aif0, aif1));
        float2 zgo = upk2(add2(ago0, ago1));
        float ig = sigm(zif.x), fg = sigm(zif.y);
        float gg = tanhx(zgo.x), og = sigm(zgo.y);
        c = fmaf(fg, c, ig * gg);
        float h = og * tanhx(c);

        hbuf[wrp][pb ^ 1][j] = make_float2(h, h);
        ystage[wrp][t & 31][j] = h * wej;        // staged FC contribution (no shfl chain)
        __syncwarp();

        if ((t & 31) == 31) {                    // transpose-reduce 32 outputs, off critical path
            float s = 0.f;
            #pragma unroll
            for (int k = 0; k < 32; k++) s += ystage[wrp][j][k];
            int tg = (t - 31) + j;
            int tout = dir ? (TT - 1 - tg) : tg;
            g_yp[dir][b * TT + tout] = s;
        }
        pb ^= 1;
    }
}

// ---------------- combine: out = yf + yr + b_eff ----------------
__global__ void combine_kernel(float* __restrict__ out) {
    int i = blockIdx.x * blockDim.x + threadIdx.x;
    if (i < BT) out[i] = g_yp[0][i] + g_yp[1][i] + g_beff;
}

extern "C" void kernel_launch(void* const* d_in, const int* in_sizes, int n_in,
                              void* d_out, int out_size) {
    const float* x     = (const float*)d_in[0];
    const float* wih_f = (const float*)d_in[1];
    const float* whh_f = (const float*)d_in[2];
    const float* bih_f = (const float*)d_in[3];
    const float* bhh_f = (const float*)d_in[4];
    const float* wih_r = (const float*)d_in[5];
    const float* whh_r = (const float*)d_in[6];
    const float* bih_r = (const float*)d_in[7];
    const float* bhh_r = (const float*)d_in[8];
    const float* fc1w  = (const float*)d_in[9];
    const float* fc1b  = (const float*)d_in[10];
    const float* fc3w  = (const float*)d_in[11];
    const float* fc3b  = (const float*)d_in[12];
    float* out = (float*)d_out;

    cudaFuncSetAttribute(proj_kernel, cudaFuncAttributeMaxDynamicSharedMemorySize, PSM_TOTAL);

    prep_kernel<<<32, 256>>>(wih_f, whh_f, bih_f, bhh_f,
                             wih_r, whh_r, bih_r, bhh_r,
                             fc1w, fc1b, fc3w, fc3b);

    dummy_kernel<<<1, 32>>>();   // slot shift: capture lands on our 4th launch
    dummy_kernel2<<<1, 32>>>();  // -> proj_kernel

    dim3 pg(PGRIDX, 2);
    proj_kernel<<<pg, 256, PSM_TOTAL>>>(x);

    lstm_kernel<<<256, 128>>>();

    combine_kernel<<<(BT + 255) / 256, 256>>>(out);
}